// round 4
// baseline (speedup 1.0000x reference)
#include <cuda_runtime.h>
#include <math.h>

#define CIN     512
#define NTAB    550            // 10+20+...+100 quadrature points
#define LOG2E   1.4426950408889634f
#define EPSQ    1e-5f
#define RPC     256            // rows per chunk (= consumer thread count)
#define NPROD   256            // producer threads (8 warps)
#define NTHR    512

__device__ __forceinline__ float ex2f(float x) {
    float r;
    asm("ex2.approx.f32 %0, %1;" : "=f"(r) : "f"(x));
    return r;
}

// Warp-specialized producer/consumer kernel.
//   warps 0-7  : dual GEMV (DRAM-bound), fill 256-row z-chunks into a
//                2-stage smem ring.
//   warps 8-15 : Beta quadrature (MUFU-bound), thread-per-row, consume chunks.
// Both roles are resident on every SM simultaneously -> DRAM streaming and
// ex2.approx issue overlap deterministically; steady state runs at DRAM rate.
__global__ void __launch_bounds__(NTHR)
beta_pipe_kernel(const float* __restrict__ x,
                 const float* __restrict__ Wa, const float* __restrict__ ba,
                 const float* __restrict__ Wb, const float* __restrict__ bb,
                 float* __restrict__ out, int B)
{
    __shared__ float2 tab[NTAB];       // (log t, log1p(-t)) * log2e
    __shared__ float2 zs[2][RPC];      // 2-stage ring of raw logits

    const int tid = threadIdx.x;
    const int nch = (B + RPC - 1) / RPC;

    if (tid < NPROD) {
        // ---------------- producer ----------------
        const int lane = tid & 31;
        const int w    = tid >> 5;
        const float biasa = ba[0], biasb = bb[0];
        const float4* wa4 = reinterpret_cast<const float4*>(Wa);
        const float4* wb4 = reinterpret_cast<const float4*>(Wb);

        int ic = 0;
        for (int c = blockIdx.x; c < nch; c += gridDim.x, ++ic) {
            const int s = ic & 1;
            if (ic >= 2)   // wait until stage s drained (consumer arrives 3+s)
                asm volatile("bar.sync %0, %1;" :: "r"(3 + s), "n"(NTHR) : "memory");

            const int rb = c * RPC + w * 32;
#pragma unroll 1
            for (int r = 0; r < 32; ++r) {
                const int row = rb + r;
                const float4* xr = reinterpret_cast<const float4*>(x)
                                 + (size_t)row * (CIN / 4);
                float sa = 0.f, sb = 0.f;
                if (row < B) {
#pragma unroll
                    for (int m = 0; m < 4; ++m) {
                        float4 xv = __ldcs(xr + lane + 32 * m);
                        float4 av = __ldg(wa4 + lane + 32 * m);
                        float4 bv = __ldg(wb4 + lane + 32 * m);
                        sa = fmaf(xv.x, av.x, fmaf(xv.y, av.y,
                             fmaf(xv.z, av.z, fmaf(xv.w, av.w, sa))));
                        sb = fmaf(xv.x, bv.x, fmaf(xv.y, bv.y,
                             fmaf(xv.z, bv.z, fmaf(xv.w, bv.w, sb))));
                    }
                }
#pragma unroll
                for (int off = 16; off; off >>= 1) {
                    sa += __shfl_xor_sync(0xffffffffu, sa, off);
                    sb += __shfl_xor_sync(0xffffffffu, sb, off);
                }
                if (lane == 0)
                    zs[s][w * 32 + r] = make_float2(sa + biasa, sb + biasb);
            }
            __threadfence_block();
            asm volatile("bar.arrive %0, %1;" :: "r"(1 + s), "n"(NTHR) : "memory");
        }
    } else {
        // ---------------- consumer ----------------
        const int ctid = tid - NPROD;

        // build quadrature table (row-independent), consumer-only barrier
        for (int k = ctid; k < NTAB; k += RPC) {
            int g = 0, off = 0;
            while (k >= off + 10 * (g + 1)) { off += 10 * (g + 1); ++g; }
            int n = 10 * (g + 1);
            int j = k - off;
            float bthr = 0.1f * (float)(g + 1);
            float step = (bthr - 2.f * EPSQ) / (float)(n - 1);
            float t = fmaf(step, (float)j, EPSQ);
            tab[k] = make_float2(logf(t) * LOG2E, log1pf(-t) * LOG2E);
        }
        asm volatile("bar.sync 5, %0;" :: "n"(RPC) : "memory");

        int ic = 0;
        for (int c = blockIdx.x; c < nch; c += gridDim.x, ++ic) {
            const int s = ic & 1;
            asm volatile("bar.sync %0, %1;" :: "r"(1 + s), "n"(NTHR) : "memory");
            const float2 z = zs[s][ctid];           // grab, then free stage
            asm volatile("bar.arrive %0, %1;" :: "r"(3 + s), "n"(NTHR) : "memory");

            const int row = c * RPC + ctid;
            if (row >= B) continue;

            const float za = z.x, zb = z.y;
            // stable softplus == jax.nn.softplus
            float spa = (za > 0.f) ? (za + log1pf(expf(-za))) : log1pf(expf(za));
            float spb = (zb > 0.f) ? (zb + log1pf(expf(-zb))) : log1pf(expf(zb));
            float alpha = fminf(1.f + spa, 100.f);
            float beta  = fminf(1.f + spb, 100.f);
            float lb = lgammaf(alpha) + lgammaf(beta) - lgammaf(alpha + beta);

            const float a1 = alpha - 1.f;
            const float b1 = beta - 1.f;
            const float c2 = -lb * LOG2E;   // dx & exp(-lbeta) cancel in the
                                            // row normalization; keep range-safe
            float cdf[10];
            const float2* tp = tab;         // pointer-walk: reg+imm LDS
#pragma unroll
            for (int g = 0; g < 10; ++g) {
                const int n = 10 * (g + 1);
                float s0 = 0.f;
#pragma unroll 10
                for (int k = 0; k < n; ++k) {
                    float2 uv = tp[k];
                    s0 += ex2f(fmaf(a1, uv.x, fmaf(b1, uv.y, c2)));
                }
                cdf[g] = s0;
                tp += n;
            }

            const float inv = 1.f / cdf[9];           // telescoping total mass
            float* o = out + (size_t)row * 10;
            float prev = 0.f;
#pragma unroll
            for (int g = 0; g < 10; ++g) {
                o[g] = (cdf[g] - prev) * inv;
                prev = cdf[g];
            }
        }
    }
}

// ---------------------------------------------------------------------------
extern "C" void kernel_launch(void* const* d_in, const int* in_sizes, int n_in,
                              void* d_out, int out_size)
{
    const float* x  = (const float*)d_in[0];
    const float* Wa = (const float*)d_in[1];
    const float* ba = (const float*)d_in[2];
    const float* Wb = (const float*)d_in[3];
    const float* bb = (const float*)d_in[4];

    int B = in_sizes[0] / CIN;
    // one persistent block per SM: 8 producer + 8 consumer warps each
    beta_pipe_kernel<<<148, NTHR>>>(x, Wa, ba, Wb, bb, (float*)d_out, B);
}

// round 6
// speedup vs baseline: 3.9109x; 3.9109x over previous
#include <cuda_runtime.h>
#include <math.h>

#define CIN     512
#define NTAB    550            // 10+20+...+100 quadrature points
#define LOG2E   1.4426950408889634f
#define EPSQ    1e-5f

__device__ __forceinline__ float ex2f(float x) {
    float r;
    asm("ex2.approx.f32 %0, %1;" : "=f"(r) : "f"(x));
    return r;
}

__device__ __forceinline__ float dot4(float4 a, float4 b, float acc) {
    return fmaf(a.x, b.x, fmaf(a.y, b.y, fmaf(a.z, b.z, fmaf(a.w, b.w, acc))));
}

// ---------------------------------------------------------------------------
// Self-contained-warp fused kernel. Each warp owns 32 consecutive rows:
//   Phase A: warp-per-row dual GEMV (DRAM stream); lane r keeps row r's
//            logits in registers after the butterfly (no smem, no barriers).
//   Phase B: thread-per-row Beta quadrature over the shared 550-pt table.
// No inter-warp coupling -> ~28 resident warps/SM drift out of phase, so
// DRAM streaming (phase A) and MUFU ex2 (phase B) overlap chip-wide.
// ---------------------------------------------------------------------------
__global__ void __launch_bounds__(256)
fused_beta_kernel(const float* __restrict__ x,
                  const float* __restrict__ Wa, const float* __restrict__ ba,
                  const float* __restrict__ Wb, const float* __restrict__ bb,
                  float* __restrict__ out, int B)
{
    __shared__ float2 tab[NTAB];       // (log t, log1p(-t)) * log2e

    const int tid  = threadIdx.x;
    const int lane = tid & 31;

    // ---- build quadrature table (row-independent) ----
    for (int k = tid; k < NTAB; k += 256) {
        int g = 0, off = 0;                       // grid g: 10(g+1) pts @ off
        while (k >= off + 10 * (g + 1)) { off += 10 * (g + 1); ++g; }
        int n = 10 * (g + 1);
        int j = k - off;
        float bthr = 0.1f * (float)(g + 1);
        float step = (bthr - 2.f * EPSQ) / (float)(n - 1);
        float t = fmaf(step, (float)j, EPSQ);
        tab[k] = make_float2(logf(t) * LOG2E, log1pf(-t) * LOG2E);
    }
    __syncthreads();

    const int base = (blockIdx.x * 8 + (tid >> 5)) * 32;  // this warp's rows
    if (base >= B) return;

    // ---- phase A: dual GEMV, weights register-resident ----
    const float4* wa4 = reinterpret_cast<const float4*>(Wa);
    const float4* wb4 = reinterpret_cast<const float4*>(Wb);
    const float4 av0 = __ldg(wa4 + lane),      av1 = __ldg(wa4 + lane + 32);
    const float4 av2 = __ldg(wa4 + lane + 64), av3 = __ldg(wa4 + lane + 96);
    const float4 bv0 = __ldg(wb4 + lane),      bv1 = __ldg(wb4 + lane + 32);
    const float4 bv2 = __ldg(wb4 + lane + 64), bv3 = __ldg(wb4 + lane + 96);
    const float biasa = ba[0], biasb = bb[0];

    float za = 0.f, zb = 0.f;                 // row 'lane' logits land here
#pragma unroll 2
    for (int r = 0; r < 32; ++r) {
        const float4* xr = reinterpret_cast<const float4*>(x)
                         + (size_t)(base + r) * (CIN / 4);
        float4 x0 = __ldcs(xr + lane);
        float4 x1 = __ldcs(xr + lane + 32);
        float4 x2 = __ldcs(xr + lane + 64);
        float4 x3 = __ldcs(xr + lane + 96);
        // tree-combine 4 partials to shorten the dependency chain
        float sa = (dot4(x0, av0, 0.f) + dot4(x1, av1, 0.f))
                 + (dot4(x2, av2, 0.f) + dot4(x3, av3, 0.f));
        float sb = (dot4(x0, bv0, 0.f) + dot4(x1, bv1, 0.f))
                 + (dot4(x2, bv2, 0.f) + dot4(x3, bv3, 0.f));
#pragma unroll
        for (int off = 16; off; off >>= 1) {
            sa += __shfl_xor_sync(0xffffffffu, sa, off);
            sb += __shfl_xor_sync(0xffffffffu, sb, off);
        }
        if (lane == r) { za = sa + biasa; zb = sb + biasb; }
    }

    // ---- phase B: thread-per-row quadrature (row = base + lane) ----
    const int row = base + lane;

    // stable softplus == jax.nn.softplus
    float spa = (za > 0.f) ? (za + log1pf(expf(-za))) : log1pf(expf(za));
    float spb = (zb > 0.f) ? (zb + log1pf(expf(-zb))) : log1pf(expf(zb));
    float alpha = fminf(1.f + spa, 100.f);
    float beta  = fminf(1.f + spb, 100.f);
    float lb = lgammaf(alpha) + lgammaf(beta) - lgammaf(alpha + beta);

    const float a1 = alpha - 1.f;
    const float b1 = beta - 1.f;
    const float c2 = -lb * LOG2E;   // dx & exp(-lbeta) cancel in normalization;
                                    // keep -lbeta inside exponent for range
    float cdf[10];
    const float2* tp = tab;         // pointer-walk: reg+imm LDS addressing
#pragma unroll
    for (int g = 0; g < 10; ++g) {
        const int n = 10 * (g + 1);
        float s0 = 0.f;
#pragma unroll 10
        for (int k = 0; k < n; ++k) {
            float2 uv = tp[k];
            s0 += ex2f(fmaf(a1, uv.x, fmaf(b1, uv.y, c2)));
        }
        cdf[g] = s0;
        tp += n;
    }

    const float inv = 1.f / cdf[9];            // telescoping total mass
    float* o = out + (size_t)row * 10;
    float prev = 0.f;
#pragma unroll
    for (int g = 0; g < 10; ++g) {
        o[g] = (cdf[g] - prev) * inv;
        prev = cdf[g];
    }
}

// ---------------------------------------------------------------------------
extern "C" void kernel_launch(void* const* d_in, const int* in_sizes, int n_in,
                              void* d_out, int out_size)
{
    const float* x  = (const float*)d_in[0];
    const float* Wa = (const float*)d_in[1];
    const float* ba = (const float*)d_in[2];
    const float* Wb = (const float*)d_in[3];
    const float* bb = (const float*)d_in[4];

    int B = in_sizes[0] / CIN;
    int blocks = (B + 255) / 256;              // 8 warps/block, 32 rows/warp
    fused_beta_kernel<<<blocks, 256>>>(x, Wa, ba, Wb, bb, (float*)d_out, B);
}